// round 9
// baseline (speedup 1.0000x reference)
#include <cuda_runtime.h>
#include <cuda.h>
#include <cuda_fp16.h>
#include <cstdint>

// ============================================================================
// LSTM cell:  gates = [X|Hx] @ [Wih|Whh]^T + bias ; LSTM epilogue.
//   B=8192, I=H=1024  ->  GEMM M=8192, N=4096, K=2048.
//
// sm_100 (non-'a') target: no tcgen05. TMA 4-stage pipeline -> ldmatrix ->
// mma.sync m16n8k16 fp16 with fp32 accumulators.
// Precision: A split into exact fp16 hi+lo (2 passes: A_hi*W + A_lo*W),
// W single fp16 -> rel_err ~= fp16 rounding of W ~ 2.8e-4 (4x under 1e-3).
// W rows permuted so gates interleave in groups of 8:
//   packed row r: gate=(r>>3)&3, h=(r>>5)*8 + (r&7)
// -> each warp's 32-col span holds [i|f|g|o] x 8 h; fully fused in-register
//    LSTM epilogue.
// ============================================================================

#define BB     8192
#define HH     1024
#define KK     2048
#define NTOT   4096

#define TILE_M 128
#define TILE_N 128
#define TILE_K 64       // fp16 elems = 128 bytes = SW128 atom row
#define K_TILES (KK / TILE_K)   // 32
#define STAGES  4

#define SUB_BYTES   (128 * 128)              // 128 rows x 128B = 16384
#define STAGE_BYTES (3 * SUB_BYTES)          // AHI ALO W = 49152
#define SM_AHI 0
#define SM_ALO 16384
#define SM_W   32768

#define SMEM_FULL0  0        // 4 x 8B
#define SMEM_EMPTY0 32       // 4 x 8B
#define SMEM_BIAS   64       // 128 floats (this CTA's packed-col biases)
#define SMEM_STAGE0 1024
#define SMEM_TOTAL  (SMEM_STAGE0 + STAGES * STAGE_BYTES)   // 197632

// ---------------- device scratch (no allocation allowed) -------------------
__device__ __align__(1024) __half g_A_hi[(size_t)BB*KK];
__device__ __align__(1024) __half g_A_lo[(size_t)BB*KK];
__device__ __align__(1024) __half g_W[(size_t)NTOT*KK];
__device__ __align__(16)   float  g_bias_p[NTOT];

// ---------------- PTX helpers ----------------------------------------------
static __device__ __forceinline__ uint32_t smem_u32(const void* p) {
    uint32_t a;
    asm("{ .reg .u64 t; cvta.to.shared.u64 t, %1; cvt.u32.u64 %0, t; }"
        : "=r"(a) : "l"(p));
    return a;
}

#define MBARRIER_INIT(addr, cnt) \
    asm volatile("mbarrier.init.shared.b64 [%0], %1;" :: "r"((uint32_t)(addr)), "r"((uint32_t)(cnt)) : "memory")

#define MBARRIER_ARRIVE(addr) \
    asm volatile("mbarrier.arrive.shared.b64 _, [%0];" :: "r"((uint32_t)(addr)) : "memory")

#define MBARRIER_EXPECT_TX(addr, tx) \
    asm volatile("mbarrier.arrive.expect_tx.shared.b64 _, [%0], %1;" :: "r"((uint32_t)(addr)), "r"((uint32_t)(tx)) : "memory")

#define MBARRIER_WAIT_PARITY(addr, ph) do {                                   \
    uint32_t _m = (uint32_t)(addr); uint32_t _p = (uint32_t)(ph);             \
    asm volatile(                                                             \
        "{\n\t.reg .pred P1;\n\t"                                             \
        "WAIT_LOOP_%=:\n\t"                                                   \
        "mbarrier.try_wait.parity.acquire.cta.shared::cta.b64 P1, [%0], %1, 0x989680;\n\t" \
        "@P1 bra.uni WAIT_DONE_%=;\n\t"                                       \
        "bra.uni WAIT_LOOP_%=;\n\t"                                           \
        "WAIT_DONE_%=:\n\t}"                                                  \
        :: "r"(_m), "r"(_p) : "memory");                                      \
} while (0)

#define TMA_LOAD_3D(smem_addr, tmap, cx_, cy_, cz_, mbar)                      \
    asm volatile(                                                              \
        "cp.async.bulk.tensor.3d.shared::cta.global.tile.mbarrier::complete_tx::bytes " \
        "[%0], [%1, {%2, %3, %4}], [%5];"                                      \
        :: "r"((uint32_t)(smem_addr)), "l"(tmap), "r"((int32_t)(cx_)),         \
           "r"((int32_t)(cy_)), "r"((int32_t)(cz_)), "r"((uint32_t)(mbar))     \
        : "memory")

#define LDMATRIX_X4(r, addr)                                                   \
    asm volatile("ldmatrix.sync.aligned.m8n8.x4.shared.b16 {%0,%1,%2,%3}, [%4];" \
        : "=r"((r)[0]), "=r"((r)[1]), "=r"((r)[2]), "=r"((r)[3])               \
        : "r"(addr))

#define LDMATRIX_X4_B(b0, b1, addr)                                            \
    asm volatile("ldmatrix.sync.aligned.m8n8.x4.shared.b16 {%0,%1,%2,%3}, [%4];" \
        : "=r"((b0)[0]), "=r"((b0)[1]), "=r"((b1)[0]), "=r"((b1)[1])           \
        : "r"(addr))

// D(f32) += A(f16,row) * B(f16,col)
#define MMA_F16(d, a, b)                                                       \
    asm volatile("mma.sync.aligned.m16n8k16.row.col.f32.f16.f16.f32 "          \
        "{%0,%1,%2,%3}, {%4,%5,%6,%7}, {%8,%9}, {%0,%1,%2,%3};"                \
        : "+f"((d)[0]), "+f"((d)[1]), "+f"((d)[2]), "+f"((d)[3])               \
        : "r"((a)[0]), "r"((a)[1]), "r"((a)[2]), "r"((a)[3]),                  \
          "r"((b)[0]), "r"((b)[1]))

static __device__ __forceinline__ float fsigmoid(float x) {
    return 1.0f / (1.0f + __expf(-x));
}
static __device__ __forceinline__ float ftanh(float x) {
    return 2.0f / (1.0f + __expf(-2.0f * x)) - 1.0f;
}

// ============================================================================
// Kernel 1: pack fp32 -> fp16 (A: exact hi/lo split; W: single), concat K,
// permute W rows, gather bias.
// Packed W row r: gate=(r>>3)&3, h=(r>>5)*8 + (r&7) -> orig = gate*1024 + h.
// ============================================================================
__global__ __launch_bounds__(512) void lstm_pack_kernel(
    const float* __restrict__ input, const float* __restrict__ hx,
    const float* __restrict__ wih,   const float* __restrict__ whh,
    const float* __restrict__ bias)
{
    int row = blockIdx.x;
    int c4  = threadIdx.x * 4;          // 0..2044

    if (row < BB) {
        const float* src = (c4 < HH) ? (input + (size_t)row * HH + c4)
                                     : (hx    + (size_t)row * HH + (c4 - HH));
        float4 v = *reinterpret_cast<const float4*>(src);
        float xs[4] = {v.x, v.y, v.z, v.w};
        __half h[4], l[4];
#pragma unroll
        for (int j = 0; j < 4; j++) {
            h[j] = __float2half(xs[j]);
            l[j] = __float2half(xs[j] - __half2float(h[j]));
        }
        __half2 h01; h01.x = h[0]; h01.y = h[1];
        __half2 h23; h23.x = h[2]; h23.y = h[3];
        __half2 l01; l01.x = l[0]; l01.y = l[1];
        __half2 l23; l23.x = l[2]; l23.y = l[3];
        __half* dhi = g_A_hi + (size_t)row * KK + c4;
        __half* dlo = g_A_lo + (size_t)row * KK + c4;
        reinterpret_cast<__half2*>(dhi)[0] = h01;
        reinterpret_cast<__half2*>(dhi)[1] = h23;
        reinterpret_cast<__half2*>(dlo)[0] = l01;
        reinterpret_cast<__half2*>(dlo)[1] = l23;
    } else {
        int r    = row - BB;
        int orig = ((r >> 3) & 3) * 1024 + ((r >> 5) * 8) + (r & 7);
        const float* src = (c4 < HH) ? (wih + (size_t)orig * HH + c4)
                                     : (whh + (size_t)orig * HH + (c4 - HH));
        if (threadIdx.x == 0) g_bias_p[r] = bias[orig];
        float4 v = *reinterpret_cast<const float4*>(src);
        __half2 w01; w01.x = __float2half(v.x); w01.y = __float2half(v.y);
        __half2 w23; w23.x = __float2half(v.z); w23.y = __float2half(v.w);
        __half* dw = g_W + (size_t)r * KK + c4;
        reinterpret_cast<__half2*>(dw)[0] = w01;
        reinterpret_cast<__half2*>(dw)[1] = w23;
    }
}

// ============================================================================
// Kernel 2: mma.sync GEMM (2-pass fp16 A-split) + fused LSTM epilogue.
// Grid: 2048 CTAs (64 mt x 32 nt), 256 threads (8 warps, 2(M) x 4(N)).
// Warp tile 64x32. TMA 4-stage ring; tid0 doubles as TMA producer.
// ============================================================================
__global__ __launch_bounds__(256) void lstm_gemm_kernel(
    const __grid_constant__ CUtensorMap mapAhi,
    const __grid_constant__ CUtensorMap mapAlo,
    const __grid_constant__ CUtensorMap mapW,
    const float* __restrict__ cx,
    float* __restrict__ out)
{
    extern __shared__ char smem[];
    const uint32_t sb = smem_u32(smem);
    const int tid  = threadIdx.x;
    const int lane = tid & 31;
    const int wid  = tid >> 5;
    const int wm   = wid & 1;      // warp row (0-1): 64 rows each
    const int wn   = wid >> 1;     // warp col (0-3): 32 cols each

    const int nt_blk = blockIdx.x & 31, mt_blk = blockIdx.x >> 5;
    const int m0  = mt_blk * TILE_M;
    const int wr0 = nt_blk * TILE_N;      // packed-W row base

    if (tid == 0) {
#pragma unroll
        for (int s = 0; s < STAGES; s++) {
            MBARRIER_INIT(sb + SMEM_FULL0  + s * 8, 1);
            MBARRIER_INIT(sb + SMEM_EMPTY0 + s * 8, 8);   // one arrive per warp
        }
    }
    if (tid < 32) {
        float4 b4 = *reinterpret_cast<const float4*>(g_bias_p + wr0 + tid * 4);
        *reinterpret_cast<float4*>(smem + SMEM_BIAS + tid * 16) = b4;
    }
    __syncthreads();

    // prologue: fill all stages
    if (tid == 0) {
#pragma unroll
        for (int s = 0; s < STAGES; s++) {
            uint32_t st = sb + SMEM_STAGE0 + s * STAGE_BYTES;
            uint32_t fb = sb + SMEM_FULL0 + s * 8;
            MBARRIER_EXPECT_TX(fb, STAGE_BYTES);
            TMA_LOAD_3D(st + SM_AHI, &mapAhi, s * TILE_K, m0,  0, fb);
            TMA_LOAD_3D(st + SM_ALO, &mapAlo, s * TILE_K, m0,  0, fb);
            TMA_LOAD_3D(st + SM_W,   &mapW,   s * TILE_K, wr0, 0, fb);
        }
    }

    // ldmatrix lane addressing (SW128 swizzle: 16B chunk ^= row&7)
    const int aRow = wm * 64 + (lane & 15);
    const int aChX = lane >> 4;               // 0/1: k-halves
    const int bN   = wn * 32 + (lane & 7) + ((lane >> 4) << 3);
    const int bChX = (lane >> 3) & 1;
    const int sXor = lane & 7;

    float d[4][4][4];                          // [mt][nt(=gate)][frag]
#pragma unroll
    for (int a = 0; a < 4; a++)
#pragma unroll
        for (int b = 0; b < 4; b++)
#pragma unroll
            for (int c = 0; c < 4; c++) d[a][b][c] = 0.0f;

    int fph[STAGES] = {0, 0, 0, 0}, eph[STAGES] = {0, 0, 0, 0};

    for (int t = 0; t < K_TILES; t++) {
        const int s = t % STAGES;
        const uint32_t st  = sb + SMEM_STAGE0 + s * STAGE_BYTES;
        MBARRIER_WAIT_PARITY(sb + SMEM_FULL0 + s * 8, fph[s]);
        fph[s] ^= 1;

#pragma unroll
        for (int ks = 0; ks < 4; ks++) {      // 4 x k16 per 64-wide tile
            uint32_t ahi[4][4], alo[4][4], bw[4][2];
#pragma unroll
            for (int mt = 0; mt < 4; mt++) {
                uint32_t off = (uint32_t)((aRow + mt * 16) * 128 +
                                          (((ks * 2 + aChX) ^ sXor) << 4));
                LDMATRIX_X4(ahi[mt], st + SM_AHI + off);
                LDMATRIX_X4(alo[mt], st + SM_ALO + off);
            }
#pragma unroll
            for (int p = 0; p < 2; p++) {
                uint32_t off = (uint32_t)((bN + p * 16) * 128 +
                                          (((ks * 2 + bChX) ^ sXor) << 4));
                LDMATRIX_X4_B(bw[2*p], bw[2*p+1], st + SM_W + off);
            }
            // pass-major: consecutive MMAs hit different accumulator tiles
#pragma unroll
            for (int mt = 0; mt < 4; mt++)
#pragma unroll
                for (int nt = 0; nt < 4; nt++) MMA_F16(d[mt][nt], ahi[mt], bw[nt]);
#pragma unroll
            for (int mt = 0; mt < 4; mt++)
#pragma unroll
                for (int nt = 0; nt < 4; nt++) MMA_F16(d[mt][nt], alo[mt], bw[nt]);
        }

        if (lane == 0) MBARRIER_ARRIVE(sb + SMEM_EMPTY0 + s * 8);
        if (tid == 0 && t + STAGES < K_TILES) {
            // stage s free once all 8 warps finished tile t
            MBARRIER_WAIT_PARITY(sb + SMEM_EMPTY0 + s * 8, eph[s]);
            eph[s] ^= 1;
            const uint32_t fb = sb + SMEM_FULL0 + s * 8;
            MBARRIER_EXPECT_TX(fb, STAGE_BYTES);
            const int k2 = (t + STAGES) * TILE_K;
            TMA_LOAD_3D(st + SM_AHI, &mapAhi, k2, m0,  0, fb);
            TMA_LOAD_3D(st + SM_ALO, &mapAlo, k2, m0,  0, fb);
            TMA_LOAD_3D(st + SM_W,   &mapW,   k2, wr0, 0, fb);
        }
    }

    // ---------------- fused in-register LSTM epilogue ------------------------
    // Warp n-span = [i|f|g|o] x 8 h; nt == gate. Thread frag (half,j):
    //   row = m0 + wm*64 + mt*16 + half*8 + lane/4,  h = hb*8 + 2*(lane&3) + j
    const float* sbias = reinterpret_cast<const float*>(smem + SMEM_BIAS);
    const int hb     = nt_blk * 4 + wn;          // h-block of 8
    const int h_base = hb * 8 + 2 * (lane & 3);
    const int rbase  = m0 + wm * 64 + (lane >> 2);
    const int bcol   = wn * 32 + 2 * (lane & 3); // + gate*8 + j

#pragma unroll
    for (int mt = 0; mt < 4; mt++) {
#pragma unroll
        for (int half = 0; half < 2; half++) {
            const int r = rbase + mt * 16 + half * 8;
            const float2 c2 = *reinterpret_cast<const float2*>(
                cx + (size_t)r * HH + h_base);
            float hyv[2], cyv[2];
#pragma unroll
            for (int j = 0; j < 2; j++) {
                const int fi = half * 2 + j;
                float gi = d[mt][0][fi] + sbias[bcol + 0  + j];
                float gf = d[mt][1][fi] + sbias[bcol + 8  + j];
                float gg = d[mt][2][fi] + sbias[bcol + 16 + j];
                float go = d[mt][3][fi] + sbias[bcol + 24 + j];
                float iv = fsigmoid(gi);
                float fv = fsigmoid(gf);
                float gv = ftanh(gg);
                float ov = fsigmoid(go);
                float cxv = (j == 0) ? c2.x : c2.y;
                float cn = fv * cxv + iv * gv;
                cyv[j] = cn;
                hyv[j] = ov * ftanh(cn);
            }
            *reinterpret_cast<float2*>(out + (size_t)r * HH + h_base) =
                make_float2(hyv[0], hyv[1]);
            *reinterpret_cast<float2*>(out + (size_t)BB * HH +
                                       (size_t)r * HH + h_base) =
                make_float2(cyv[0], cyv[1]);
        }
    }
}

// ============================================================================
// Host launch
// ============================================================================
typedef CUresult (*cuTensorMapEncodeTiled_t)(
    CUtensorMap*, CUtensorMapDataType, cuuint32_t, void*,
    const cuuint64_t*, const cuuint64_t*, const cuuint32_t*, const cuuint32_t*,
    CUtensorMapInterleave, CUtensorMapSwizzle, CUtensorMapL2promotion,
    CUtensorMapFloatOOBfill);

static void encode_map(cuTensorMapEncodeTiled_t fn, CUtensorMap* m, void* base,
                       unsigned long long rows)
{
    cuuint64_t dims[3]    = {(cuuint64_t)KK, rows, 1};
    cuuint64_t strides[2] = {(cuuint64_t)KK * 2, rows * (cuuint64_t)KK * 2};
    cuuint32_t box[3]     = {TILE_K, 128, 1};
    cuuint32_t es[3]      = {1, 1, 1};
    fn(m, CU_TENSOR_MAP_DATA_TYPE_FLOAT16, 3, base, dims, strides, box, es,
       CU_TENSOR_MAP_INTERLEAVE_NONE, CU_TENSOR_MAP_SWIZZLE_128B,
       CU_TENSOR_MAP_L2_PROMOTION_L2_128B, CU_TENSOR_MAP_FLOAT_OOB_FILL_NONE);
}

extern "C" void kernel_launch(void* const* d_in, const int* in_sizes, int n_in,
                              void* d_out, int out_size)
{
    const float* input = (const float*)d_in[0];
    const float* hx    = (const float*)d_in[1];
    const float* cx    = (const float*)d_in[2];
    const float* wih   = (const float*)d_in[3];
    const float* whh   = (const float*)d_in[4];
    const float* bias  = (const float*)d_in[5];
    float* out = (float*)d_out;
    (void)in_sizes; (void)n_in; (void)out_size;

    void *pAhi, *pAlo, *pW;
    cudaGetSymbolAddress(&pAhi, g_A_hi);
    cudaGetSymbolAddress(&pAlo, g_A_lo);
    cudaGetSymbolAddress(&pW,   g_W);

    cuTensorMapEncodeTiled_t enc = nullptr;
    cudaDriverEntryPointQueryResult qr;
    cudaGetDriverEntryPoint("cuTensorMapEncodeTiled", (void**)&enc,
                            cudaEnableDefault, &qr);

    CUtensorMap mAhi, mAlo, mW;
    encode_map(enc, &mAhi, pAhi, BB);
    encode_map(enc, &mAlo, pAlo, BB);
    encode_map(enc, &mW,   pW,   NTOT);

    lstm_pack_kernel<<<BB + NTOT, 512>>>(input, hx, wih, whh, bias);

    cudaFuncSetAttribute(lstm_gemm_kernel,
                         cudaFuncAttributeMaxDynamicSharedMemorySize, SMEM_TOTAL);
    lstm_gemm_kernel<<<(BB / TILE_M) * (NTOT / TILE_N), 256, SMEM_TOTAL>>>(
        mAhi, mAlo, mW, cx, out);
}

// round 10
// speedup vs baseline: 1.6930x; 1.6930x over previous
#include <cuda_runtime.h>
#include <cuda.h>
#include <cuda_fp16.h>
#include <cstdint>

// ============================================================================
// LSTM cell:  gates = [X|Hx] @ [Wih|Whh]^T + bias ; LSTM epilogue.
//   B=8192, I=H=1024  ->  GEMM M=8192, N=4096, K=2048.
//
// sm_100 (non-'a') target: no tcgen05. TMA 4-stage pipeline -> ldmatrix ->
// mma.sync m16n8k16 fp16, fp32 accum. SINGLE fp16 pass (A and W both fp16):
// rel_err ~ 1.9e-4 (W-only measured 1.34e-4; A adds in quadrature), 5x under
// the 1e-3 gate.
// CTA 128x256, warp tile 64x64 (8 warps 2Mx4N): MMA:LDSM.x4 = 4.0.
// W rows permuted so gates interleave in groups of 8:
//   packed row r: gate=(r>>3)&3, h=(r>>5)*8 + (r&7)
// -> each warp 32-col group holds [i|f|g|o] x 8 h; fused in-register epilogue.
// ============================================================================

#define BB     8192
#define HH     1024
#define KK     2048
#define NTOT   4096

#define TILE_M 128
#define TILE_N 256
#define TILE_K 64       // fp16 elems = 128 bytes = SW128 atom row
#define K_TILES (KK / TILE_K)   // 32
#define STAGES  4

#define A_BYTES     (128 * 128)              // 16384
#define W_BYTES     (256 * 128)              // 32768
#define STAGE_BYTES (A_BYTES + W_BYTES)      // 49152
#define SM_A 0
#define SM_W 16384

#define SMEM_FULL0  0        // 4 x 8B
#define SMEM_EMPTY0 32       // 4 x 8B
#define SMEM_BIAS   64       // 256 floats = 1024B
#define SMEM_STAGE0 2048
#define SMEM_TOTAL  (SMEM_STAGE0 + STAGES * STAGE_BYTES)   // 198656

// ---------------- device scratch (no allocation allowed) -------------------
__device__ __align__(1024) __half g_A[(size_t)BB*KK];
__device__ __align__(1024) __half g_W[(size_t)NTOT*KK];
__device__ __align__(16)   float  g_bias_p[NTOT];

// ---------------- PTX helpers ----------------------------------------------
static __device__ __forceinline__ uint32_t smem_u32(const void* p) {
    uint32_t a;
    asm("{ .reg .u64 t; cvta.to.shared.u64 t, %1; cvt.u32.u64 %0, t; }"
        : "=r"(a) : "l"(p));
    return a;
}

#define MBARRIER_INIT(addr, cnt) \
    asm volatile("mbarrier.init.shared.b64 [%0], %1;" :: "r"((uint32_t)(addr)), "r"((uint32_t)(cnt)) : "memory")

#define MBARRIER_ARRIVE(addr) \
    asm volatile("mbarrier.arrive.shared.b64 _, [%0];" :: "r"((uint32_t)(addr)) : "memory")

#define MBARRIER_EXPECT_TX(addr, tx) \
    asm volatile("mbarrier.arrive.expect_tx.shared.b64 _, [%0], %1;" :: "r"((uint32_t)(addr)), "r"((uint32_t)(tx)) : "memory")

#define MBARRIER_WAIT_PARITY(addr, ph) do {                                   \
    uint32_t _m = (uint32_t)(addr); uint32_t _p = (uint32_t)(ph);             \
    asm volatile(                                                             \
        "{\n\t.reg .pred P1;\n\t"                                             \
        "WAIT_LOOP_%=:\n\t"                                                   \
        "mbarrier.try_wait.parity.acquire.cta.shared::cta.b64 P1, [%0], %1, 0x989680;\n\t" \
        "@P1 bra.uni WAIT_DONE_%=;\n\t"                                       \
        "bra.uni WAIT_LOOP_%=;\n\t"                                           \
        "WAIT_DONE_%=:\n\t}"                                                  \
        :: "r"(_m), "r"(_p) : "memory");                                      \
} while (0)

#define TMA_LOAD_3D(smem_addr, tmap, cx_, cy_, cz_, mbar)                      \
    asm volatile(                                                              \
        "cp.async.bulk.tensor.3d.shared::cta.global.tile.mbarrier::complete_tx::bytes " \
        "[%0], [%1, {%2, %3, %4}], [%5];"                                      \
        :: "r"((uint32_t)(smem_addr)), "l"(tmap), "r"((int32_t)(cx_)),         \
           "r"((int32_t)(cy_)), "r"((int32_t)(cz_)), "r"((uint32_t)(mbar))     \
        : "memory")

#define LDMATRIX_X4(r, addr)                                                   \
    asm volatile("ldmatrix.sync.aligned.m8n8.x4.shared.b16 {%0,%1,%2,%3}, [%4];" \
        : "=r"((r)[0]), "=r"((r)[1]), "=r"((r)[2]), "=r"((r)[3])               \
        : "r"(addr))

#define LDMATRIX_X4_B(b0, b1, addr)                                            \
    asm volatile("ldmatrix.sync.aligned.m8n8.x4.shared.b16 {%0,%1,%2,%3}, [%4];" \
        : "=r"((b0)[0]), "=r"((b0)[1]), "=r"((b1)[0]), "=r"((b1)[1])           \
        : "r"(addr))

#define MMA_F16(d, a, b)                                                       \
    asm volatile("mma.sync.aligned.m16n8k16.row.col.f32.f16.f16.f32 "          \
        "{%0,%1,%2,%3}, {%4,%5,%6,%7}, {%8,%9}, {%0,%1,%2,%3};"                \
        : "+f"((d)[0]), "+f"((d)[1]), "+f"((d)[2]), "+f"((d)[3])               \
        : "r"((a)[0]), "r"((a)[1]), "r"((a)[2]), "r"((a)[3]),                  \
          "r"((b)[0]), "r"((b)[1]))

static __device__ __forceinline__ float fsigmoid(float x) {
    return 1.0f / (1.0f + __expf(-x));
}
static __device__ __forceinline__ float ftanh(float x) {
    return 2.0f / (1.0f + __expf(-2.0f * x)) - 1.0f;
}

// ============================================================================
// Kernel 1: pack fp32 -> fp16, concat K, permute W rows, gather bias.
// Packed W row r: gate=(r>>3)&3, h=(r>>5)*8 + (r&7) -> orig = gate*1024 + h.
// ============================================================================
__global__ __launch_bounds__(512) void lstm_pack_kernel(
    const float* __restrict__ input, const float* __restrict__ hx,
    const float* __restrict__ wih,   const float* __restrict__ whh,
    const float* __restrict__ bias)
{
    int row = blockIdx.x;
    int c4  = threadIdx.x * 4;          // 0..2044
    const float* src;
    __half* dst;

    if (row < BB) {
        src = (c4 < HH) ? (input + (size_t)row * HH + c4)
                        : (hx    + (size_t)row * HH + (c4 - HH));
        dst = g_A + (size_t)row * KK + c4;
    } else {
        int r    = row - BB;
        int orig = ((r >> 3) & 3) * 1024 + ((r >> 5) * 8) + (r & 7);
        src = (c4 < HH) ? (wih + (size_t)orig * HH + c4)
                        : (whh + (size_t)orig * HH + (c4 - HH));
        dst = g_W + (size_t)r * KK + c4;
        if (threadIdx.x == 0) g_bias_p[r] = bias[orig];
    }

    float4 v = *reinterpret_cast<const float4*>(src);
    __half2 w01; w01.x = __float2half(v.x); w01.y = __float2half(v.y);
    __half2 w23; w23.x = __float2half(v.z); w23.y = __float2half(v.w);
    reinterpret_cast<__half2*>(dst)[0] = w01;
    reinterpret_cast<__half2*>(dst)[1] = w23;
}

// ============================================================================
// Kernel 2: mma.sync fp16 GEMM (single pass) + fused LSTM epilogue.
// Grid: 1024 CTAs (64 mt x 16 nt), 256 threads (8 warps, 2(M) x 4(N)).
// Warp tile 64x64. TMA 4-stage ring; tid0 doubles as TMA producer.
// ============================================================================
__global__ __launch_bounds__(256, 1) void lstm_gemm_kernel(
    const __grid_constant__ CUtensorMap mapA,
    const __grid_constant__ CUtensorMap mapW,
    const float* __restrict__ cx,
    float* __restrict__ out)
{
    extern __shared__ char smem[];
    const uint32_t sb = smem_u32(smem);
    const int tid  = threadIdx.x;
    const int lane = tid & 31;
    const int wid  = tid >> 5;
    const int wm   = wid & 1;      // warp row (0-1): 64 rows each
    const int wn   = wid >> 1;     // warp col (0-3): 64 cols each

    const int nt_blk = blockIdx.x & 15, mt_blk = blockIdx.x >> 4;
    const int m0  = mt_blk * TILE_M;
    const int wr0 = nt_blk * TILE_N;      // packed-W row base

    if (tid == 0) {
#pragma unroll
        for (int s = 0; s < STAGES; s++) {
            MBARRIER_INIT(sb + SMEM_FULL0  + s * 8, 1);
            MBARRIER_INIT(sb + SMEM_EMPTY0 + s * 8, 8);   // one arrive per warp
        }
    }
    if (tid < 64) {
        float4 b4 = *reinterpret_cast<const float4*>(g_bias_p + wr0 + tid * 4);
        *reinterpret_cast<float4*>(smem + SMEM_BIAS + tid * 16) = b4;
    }
    __syncthreads();

    // prologue: fill all stages
    if (tid == 0) {
#pragma unroll
        for (int s = 0; s < STAGES; s++) {
            uint32_t st = sb + SMEM_STAGE0 + s * STAGE_BYTES;
            uint32_t fb = sb + SMEM_FULL0 + s * 8;
            MBARRIER_EXPECT_TX(fb, STAGE_BYTES);
            TMA_LOAD_3D(st + SM_A, &mapA, s * TILE_K, m0,  0, fb);
            TMA_LOAD_3D(st + SM_W, &mapW, s * TILE_K, wr0, 0, fb);
        }
    }

    // ldmatrix lane addressing (SW128 swizzle: 16B chunk ^= row&7)
    const int aRow = wm * 64 + (lane & 15);
    const int aChX = lane >> 4;               // 0/1: k-halves
    const int bN   = (lane & 7) + ((lane >> 4) << 3);
    const int bChX = (lane >> 3) & 1;
    const int sXor = lane & 7;

    float d[4][8][4];                          // [mt][p*4 + gate][frag]
#pragma unroll
    for (int a = 0; a < 4; a++)
#pragma unroll
        for (int b = 0; b < 8; b++)
#pragma unroll
            for (int c = 0; c < 4; c++) d[a][b][c] = 0.0f;

    int fph[STAGES] = {0, 0, 0, 0}, eph[STAGES] = {0, 0, 0, 0};

    for (int t = 0; t < K_TILES; t++) {
        const int s = t % STAGES;
        const uint32_t st  = sb + SMEM_STAGE0 + s * STAGE_BYTES;
        MBARRIER_WAIT_PARITY(sb + SMEM_FULL0 + s * 8, fph[s]);
        fph[s] ^= 1;

#pragma unroll
        for (int ks = 0; ks < 4; ks++) {      // 4 x k16 per 64-deep tile
            uint32_t a[4][4], bw[8][2];
#pragma unroll
            for (int mt = 0; mt < 4; mt++) {
                uint32_t off = (uint32_t)((aRow + mt * 16) * 128 +
                                          (((ks * 2 + aChX) ^ sXor) << 4));
                LDMATRIX_X4(a[mt], st + SM_A + off);
            }
#pragma unroll
            for (int p = 0; p < 2; p++)       // 32-col gate groups
#pragma unroll
                for (int q = 0; q < 2; q++) { // 16-row (2-gate) batches
                    uint32_t off = (uint32_t)(
                        (wn * 64 + p * 32 + q * 16 + bN) * 128 +
                        (((ks * 2 + bChX) ^ sXor) << 4));
                    LDMATRIX_X4_B(bw[p*4 + q*2], bw[p*4 + q*2 + 1],
                                  st + SM_W + off);
                }
#pragma unroll
            for (int mt = 0; mt < 4; mt++)
#pragma unroll
                for (int j = 0; j < 8; j++) MMA_F16(d[mt][j], a[mt], bw[j]);
        }

        if (lane == 0) MBARRIER_ARRIVE(sb + SMEM_EMPTY0 + s * 8);
        if (tid == 0 && t + STAGES < K_TILES) {
            MBARRIER_WAIT_PARITY(sb + SMEM_EMPTY0 + s * 8, eph[s]);
            eph[s] ^= 1;
            const uint32_t fb = sb + SMEM_FULL0 + s * 8;
            MBARRIER_EXPECT_TX(fb, STAGE_BYTES);
            const int k2 = (t + STAGES) * TILE_K;
            TMA_LOAD_3D(st + SM_A, &mapA, k2, m0,  0, fb);
            TMA_LOAD_3D(st + SM_W, &mapW, k2, wr0, 0, fb);
        }
    }

    // ---------------- fused in-register LSTM epilogue ------------------------
    // Warp covers 64 packed cols = 2 groups of [i|f|g|o] x 8 h.
    // Group p: h-block = nt_blk*8 + wn*2 + p.  Thread frag (half,j):
    //   row = m0 + wm*64 + mt*16 + half*8 + lane/4,  h = hblk*8 + 2*(lane&3)+j
    const float* sbias = reinterpret_cast<const float*>(smem + SMEM_BIAS);
    const int rbase = m0 + wm * 64 + (lane >> 2);

#pragma unroll
    for (int mt = 0; mt < 4; mt++) {
#pragma unroll
        for (int half = 0; half < 2; half++) {
            const int r = rbase + mt * 16 + half * 8;
#pragma unroll
            for (int p = 0; p < 2; p++) {
                const int h_base = (nt_blk * 8 + wn * 2 + p) * 8
                                 + 2 * (lane & 3);
                const int bcol   = wn * 64 + p * 32 + 2 * (lane & 3);
                const float2 c2 = *reinterpret_cast<const float2*>(
                    cx + (size_t)r * HH + h_base);
                float hyv[2], cyv[2];
#pragma unroll
                for (int j = 0; j < 2; j++) {
                    const int fi = half * 2 + j;
                    float gi = d[mt][p*4 + 0][fi] + sbias[bcol + 0  + j];
                    float gf = d[mt][p*4 + 1][fi] + sbias[bcol + 8  + j];
                    float gg = d[mt][p*4 + 2][fi] + sbias[bcol + 16 + j];
                    float go = d[mt][p*4 + 3][fi] + sbias[bcol + 24 + j];
                    float iv = fsigmoid(gi);
                    float fv = fsigmoid(gf);
                    float gv = ftanh(gg);
                    float ov = fsigmoid(go);
                    float cxv = (j == 0) ? c2.x : c2.y;
                    float cn = fv * cxv + iv * gv;
                    cyv[j] = cn;
                    hyv[j] = ov * ftanh(cn);
                }
                *reinterpret_cast<float2*>(out + (size_t)r * HH + h_base) =
                    make_float2(hyv[0], hyv[1]);
                *reinterpret_cast<float2*>(out + (size_t)BB * HH +
                                           (size_t)r * HH + h_base) =
                    make_float2(cyv[0], cyv[1]);
            }
        }
    }
}

// ============================================================================
// Host launch
// ============================================================================
typedef CUresult (*cuTensorMapEncodeTiled_t)(
    CUtensorMap*, CUtensorMapDataType, cuuint32_t, void*,
    const cuuint64_t*, const cuuint64_t*, const cuuint32_t*, const cuuint32_t*,
    CUtensorMapInterleave, CUtensorMapSwizzle, CUtensorMapL2promotion,
    CUtensorMapFloatOOBfill);

static void encode_map(cuTensorMapEncodeTiled_t fn, CUtensorMap* m, void* base,
                       unsigned long long rows, unsigned box_rows)
{
    cuuint64_t dims[3]    = {(cuuint64_t)KK, rows, 1};
    cuuint64_t strides[2] = {(cuuint64_t)KK * 2, rows * (cuuint64_t)KK * 2};
    cuuint32_t box[3]     = {TILE_K, box_rows, 1};
    cuuint32_t es[3]      = {1, 1, 1};
    fn(m, CU_TENSOR_MAP_DATA_TYPE_FLOAT16, 3, base, dims, strides, box, es,
       CU_TENSOR_MAP_INTERLEAVE_NONE, CU_TENSOR_MAP_SWIZZLE_128B,
       CU_TENSOR_MAP_L2_PROMOTION_L2_128B, CU_TENSOR_MAP_FLOAT_OOB_FILL_NONE);
}

extern "C" void kernel_launch(void* const* d_in, const int* in_sizes, int n_in,
                              void* d_out, int out_size)
{
    const float* input = (const float*)d_in[0];
    const float* hx    = (const float*)d_in[1];
    const float* cx    = (const float*)d_in[2];
    const float* wih   = (const float*)d_in[3];
    const float* whh   = (const float*)d_in[4];
    const float* bias  = (const float*)d_in[5];
    float* out = (float*)d_out;
    (void)in_sizes; (void)n_in; (void)out_size;

    void *pA, *pW;
    cudaGetSymbolAddress(&pA, g_A);
    cudaGetSymbolAddress(&pW, g_W);

    cuTensorMapEncodeTiled_t enc = nullptr;
    cudaDriverEntryPointQueryResult qr;
    cudaGetDriverEntryPoint("cuTensorMapEncodeTiled", (void**)&enc,
                            cudaEnableDefault, &qr);

    CUtensorMap mA, mW;
    encode_map(enc, &mA, pA, BB,   128);
    encode_map(enc, &mW, pW, NTOT, 256);

    lstm_pack_kernel<<<BB + NTOT, 512>>>(input, hx, wih, whh, bias);

    cudaFuncSetAttribute(lstm_gemm_kernel,
                         cudaFuncAttributeMaxDynamicSharedMemorySize, SMEM_TOTAL);
    lstm_gemm_kernel<<<(BB / TILE_M) * (NTOT / TILE_N), 256, SMEM_TOTAL>>>(
        mA, mW, cx, out);
}

// round 11
// speedup vs baseline: 1.8195x; 1.0747x over previous
#include <cuda_runtime.h>
#include <cuda.h>
#include <cuda_fp16.h>
#include <cstdint>

// ============================================================================
// LSTM cell:  gates = [X|Hx] @ [Wih|Whh]^T + bias ; LSTM epilogue.
//   B=8192, I=H=1024  ->  GEMM M=8192, N=4096, K=2048.
//
// sm_100 (non-'a') target: no tcgen05. TMA 4-stage pipeline -> ldmatrix ->
// mma.sync m16n8k16 fp16, fp32 accum. Single fp16 pass (rel_err ~2e-4).
// CTA 128x256, 512 threads = 16 warps (2M x 8N), warp tile 64x32:
// 4 warps/SMSP so LDSM phases of one warp overlap MMA phases of others.
// W rows permuted so gates interleave in groups of 8:
//   packed row r: gate=(r>>3)&3, h=(r>>5)*8 + (r&7)
// -> each warp's 32-col span = [i|f|g|o] x 8 h; fused in-register epilogue.
// ============================================================================

#define BB     8192
#define HH     1024
#define KK     2048
#define NTOT   4096

#define TILE_M 128
#define TILE_N 256
#define TILE_K 64       // fp16 elems = 128 bytes = SW128 atom row
#define K_TILES (KK / TILE_K)   // 32
#define STAGES  4

#define A_BYTES     (128 * 128)              // 16384
#define W_BYTES     (256 * 128)              // 32768
#define STAGE_BYTES (A_BYTES + W_BYTES)      // 49152
#define SM_A 0
#define SM_W 16384

#define SMEM_FULL0  0        // 4 x 8B
#define SMEM_EMPTY0 32       // 4 x 8B
#define SMEM_BIAS   64       // 256 floats = 1024B
#define SMEM_STAGE0 2048
#define SMEM_TOTAL  (SMEM_STAGE0 + STAGES * STAGE_BYTES)   // 198656

// ---------------- device scratch (no allocation allowed) -------------------
__device__ __align__(1024) __half g_A[(size_t)BB*KK];
__device__ __align__(1024) __half g_W[(size_t)NTOT*KK];
__device__ __align__(16)   float  g_bias_p[NTOT];

// ---------------- PTX helpers ----------------------------------------------
static __device__ __forceinline__ uint32_t smem_u32(const void* p) {
    uint32_t a;
    asm("{ .reg .u64 t; cvta.to.shared.u64 t, %1; cvt.u32.u64 %0, t; }"
        : "=r"(a) : "l"(p));
    return a;
}

#define MBARRIER_INIT(addr, cnt) \
    asm volatile("mbarrier.init.shared.b64 [%0], %1;" :: "r"((uint32_t)(addr)), "r"((uint32_t)(cnt)) : "memory")

#define MBARRIER_ARRIVE(addr) \
    asm volatile("mbarrier.arrive.shared.b64 _, [%0];" :: "r"((uint32_t)(addr)) : "memory")

#define MBARRIER_EXPECT_TX(addr, tx) \
    asm volatile("mbarrier.arrive.expect_tx.shared.b64 _, [%0], %1;" :: "r"((uint32_t)(addr)), "r"((uint32_t)(tx)) : "memory")

#define MBARRIER_WAIT_PARITY(addr, ph) do {                                   \
    uint32_t _m = (uint32_t)(addr); uint32_t _p = (uint32_t)(ph);             \
    asm volatile(                                                             \
        "{\n\t.reg .pred P1;\n\t"                                             \
        "WAIT_LOOP_%=:\n\t"                                                   \
        "mbarrier.try_wait.parity.acquire.cta.shared::cta.b64 P1, [%0], %1, 0x989680;\n\t" \
        "@P1 bra.uni WAIT_DONE_%=;\n\t"                                       \
        "bra.uni WAIT_LOOP_%=;\n\t"                                           \
        "WAIT_DONE_%=:\n\t}"                                                  \
        :: "r"(_m), "r"(_p) : "memory");                                      \
} while (0)

#define TMA_LOAD_3D(smem_addr, tmap, cx_, cy_, cz_, mbar)                      \
    asm volatile(                                                              \
        "cp.async.bulk.tensor.3d.shared::cta.global.tile.mbarrier::complete_tx::bytes " \
        "[%0], [%1, {%2, %3, %4}], [%5];"                                      \
        :: "r"((uint32_t)(smem_addr)), "l"(tmap), "r"((int32_t)(cx_)),         \
           "r"((int32_t)(cy_)), "r"((int32_t)(cz_)), "r"((uint32_t)(mbar))     \
        : "memory")

#define LDMATRIX_X4(r, addr)                                                   \
    asm volatile("ldmatrix.sync.aligned.m8n8.x4.shared.b16 {%0,%1,%2,%3}, [%4];" \
        : "=r"((r)[0]), "=r"((r)[1]), "=r"((r)[2]), "=r"((r)[3])               \
        : "r"(addr))

#define LDMATRIX_X4_B(b0, b1, addr)                                            \
    asm volatile("ldmatrix.sync.aligned.m8n8.x4.shared.b16 {%0,%1,%2,%3}, [%4];" \
        : "=r"((b0)[0]), "=r"((b0)[1]), "=r"((b1)[0]), "=r"((b1)[1])           \
        : "r"(addr))

#define MMA_F16(d, a, b)                                                       \
    asm volatile("mma.sync.aligned.m16n8k16.row.col.f32.f16.f16.f32 "          \
        "{%0,%1,%2,%3}, {%4,%5,%6,%7}, {%8,%9}, {%0,%1,%2,%3};"                \
        : "+f"((d)[0]), "+f"((d)[1]), "+f"((d)[2]), "+f"((d)[3])               \
        : "r"((a)[0]), "r"((a)[1]), "r"((a)[2]), "r"((a)[3]),                  \
          "r"((b)[0]), "r"((b)[1]))

static __device__ __forceinline__ float fsigmoid(float x) {
    return 1.0f / (1.0f + __expf(-x));
}
static __device__ __forceinline__ float ftanh(float x) {
    return 2.0f / (1.0f + __expf(-2.0f * x)) - 1.0f;
}

// ============================================================================
// Kernel 1: pack fp32 -> fp16, concat K, permute W rows, gather bias.
// Packed W row r: gate=(r>>3)&3, h=(r>>5)*8 + (r&7) -> orig = gate*1024 + h.
// ============================================================================
__global__ __launch_bounds__(512) void lstm_pack_kernel(
    const float* __restrict__ input, const float* __restrict__ hx,
    const float* __restrict__ wih,   const float* __restrict__ whh,
    const float* __restrict__ bias)
{
    int row = blockIdx.x;
    int c4  = threadIdx.x * 4;          // 0..2044
    const float* src;
    __half* dst;

    if (row < BB) {
        src = (c4 < HH) ? (input + (size_t)row * HH + c4)
                        : (hx    + (size_t)row * HH + (c4 - HH));
        dst = g_A + (size_t)row * KK + c4;
    } else {
        int r    = row - BB;
        int orig = ((r >> 3) & 3) * 1024 + ((r >> 5) * 8) + (r & 7);
        src = (c4 < HH) ? (wih + (size_t)orig * HH + c4)
                        : (whh + (size_t)orig * HH + (c4 - HH));
        dst = g_W + (size_t)r * KK + c4;
        if (threadIdx.x == 0) g_bias_p[r] = bias[orig];
    }

    float4 v = *reinterpret_cast<const float4*>(src);
    __half2 w01; w01.x = __float2half(v.x); w01.y = __float2half(v.y);
    __half2 w23; w23.x = __float2half(v.z); w23.y = __float2half(v.w);
    reinterpret_cast<__half2*>(dst)[0] = w01;
    reinterpret_cast<__half2*>(dst)[1] = w23;
}

// ============================================================================
// Kernel 2: mma.sync fp16 GEMM (single pass) + fused LSTM epilogue.
// Grid: 1024 CTAs (64 mt x 16 nt), 512 threads (16 warps, 2(M) x 8(N)).
// Warp tile 64x32. TMA 4-stage ring; tid0 doubles as TMA producer.
// ============================================================================
__global__ __launch_bounds__(512, 1) void lstm_gemm_kernel(
    const __grid_constant__ CUtensorMap mapA,
    const __grid_constant__ CUtensorMap mapW,
    const float* __restrict__ cx,
    float* __restrict__ out)
{
    extern __shared__ char smem[];
    const uint32_t sb = smem_u32(smem);
    const int tid  = threadIdx.x;
    const int lane = tid & 31;
    const int wid  = tid >> 5;
    const int wm   = wid >> 3;     // warp row (0-1): 64 rows each
    const int wn   = wid & 7;      // warp col (0-7): 32 cols each

    const int nt_blk = blockIdx.x & 15, mt_blk = blockIdx.x >> 4;
    const int m0  = mt_blk * TILE_M;
    const int wr0 = nt_blk * TILE_N;      // packed-W row base

    if (tid == 0) {
#pragma unroll
        for (int s = 0; s < STAGES; s++) {
            MBARRIER_INIT(sb + SMEM_FULL0  + s * 8, 1);
            MBARRIER_INIT(sb + SMEM_EMPTY0 + s * 8, 16);  // one arrive per warp
        }
    }
    if (tid < 64) {
        float4 b4 = *reinterpret_cast<const float4*>(g_bias_p + wr0 + tid * 4);
        *reinterpret_cast<float4*>(smem + SMEM_BIAS + tid * 16) = b4;
    }
    __syncthreads();

    // prologue: fill all stages
    if (tid == 0) {
#pragma unroll
        for (int s = 0; s < STAGES; s++) {
            uint32_t st = sb + SMEM_STAGE0 + s * STAGE_BYTES;
            uint32_t fb = sb + SMEM_FULL0 + s * 8;
            MBARRIER_EXPECT_TX(fb, STAGE_BYTES);
            TMA_LOAD_3D(st + SM_A, &mapA, s * TILE_K, m0,  0, fb);
            TMA_LOAD_3D(st + SM_W, &mapW, s * TILE_K, wr0, 0, fb);
        }
    }

    // ldmatrix lane addressing (SW128 swizzle: 16B chunk ^= row&7)
    const int aRow = wm * 64 + (lane & 15);
    const int aChX = lane >> 4;               // 0/1: k-halves
    const int bN   = (lane & 7) + ((lane >> 4) << 3);
    const int bChX = (lane >> 3) & 1;
    const int sXor = lane & 7;

    float d[4][4][4];                          // [mt][gate][frag]
#pragma unroll
    for (int a = 0; a < 4; a++)
#pragma unroll
        for (int b = 0; b < 4; b++)
#pragma unroll
            for (int c = 0; c < 4; c++) d[a][b][c] = 0.0f;

    int fph[STAGES] = {0, 0, 0, 0}, eph[STAGES] = {0, 0, 0, 0};

    for (int t = 0; t < K_TILES; t++) {
        const int s = t % STAGES;
        const uint32_t st  = sb + SMEM_STAGE0 + s * STAGE_BYTES;
        MBARRIER_WAIT_PARITY(sb + SMEM_FULL0 + s * 8, fph[s]);
        fph[s] ^= 1;

#pragma unroll
        for (int ks = 0; ks < 4; ks++) {      // 4 x k16 per 64-deep tile
            uint32_t a[4][4], bw[4][2];
#pragma unroll
            for (int mt = 0; mt < 4; mt++) {
                uint32_t off = (uint32_t)((aRow + mt * 16) * 128 +
                                          (((ks * 2 + aChX) ^ sXor) << 4));
                LDMATRIX_X4(a[mt], st + SM_A + off);
            }
#pragma unroll
            for (int q = 0; q < 2; q++) {     // 16-row (2-gate) batches
                uint32_t off = (uint32_t)((wn * 32 + q * 16 + bN) * 128 +
                                          (((ks * 2 + bChX) ^ sXor) << 4));
                LDMATRIX_X4_B(bw[q*2], bw[q*2 + 1], st + SM_W + off);
            }
#pragma unroll
            for (int mt = 0; mt < 4; mt++)
#pragma unroll
                for (int g = 0; g < 4; g++) MMA_F16(d[mt][g], a[mt], bw[g]);
        }

        if (lane == 0) MBARRIER_ARRIVE(sb + SMEM_EMPTY0 + s * 8);
        if (tid == 0 && t + STAGES < K_TILES) {
            MBARRIER_WAIT_PARITY(sb + SMEM_EMPTY0 + s * 8, eph[s]);
            eph[s] ^= 1;
            const uint32_t fb = sb + SMEM_FULL0 + s * 8;
            MBARRIER_EXPECT_TX(fb, STAGE_BYTES);
            const int k2 = (t + STAGES) * TILE_K;
            TMA_LOAD_3D(st + SM_A, &mapA, k2, m0,  0, fb);
            TMA_LOAD_3D(st + SM_W, &mapW, k2, wr0, 0, fb);
        }
    }

    // ---------------- fused in-register LSTM epilogue ------------------------
    // Warp's 32 cols = [i|f|g|o] x 8 h;  h-block = nt_blk*8 + wn.
    // Thread frag (half,j): row = m0 + wm*64 + mt*16 + half*8 + lane/4,
    //                       h   = hblk*8 + 2*(lane&3) + j
    const float* sbias = reinterpret_cast<const float*>(smem + SMEM_BIAS);
    const int rbase  = m0 + wm * 64 + (lane >> 2);
    const int h_base = (nt_blk * 8 + wn) * 8 + 2 * (lane & 3);
    const int bcol   = wn * 32 + 2 * (lane & 3);

#pragma unroll
    for (int mt = 0; mt < 4; mt++) {
#pragma unroll
        for (int half = 0; half < 2; half++) {
            const int r = rbase + mt * 16 + half * 8;
            const float2 c2 = *reinterpret_cast<const float2*>(
                cx + (size_t)r * HH + h_base);
            float hyv[2], cyv[2];
#pragma unroll
            for (int j = 0; j < 2; j++) {
                const int fi = half * 2 + j;
                float gi = d[mt][0][fi] + sbias[bcol + 0  + j];
                float gf = d[mt][1][fi] + sbias[bcol + 8  + j];
                float gg = d[mt][2][fi] + sbias[bcol + 16 + j];
                float go = d[mt][3][fi] + sbias[bcol + 24 + j];
                float iv = fsigmoid(gi);
                float fv = fsigmoid(gf);
                float gv = ftanh(gg);
                float ov = fsigmoid(go);
                float cxv = (j == 0) ? c2.x : c2.y;
                float cn = fv * cxv + iv * gv;
                cyv[j] = cn;
                hyv[j] = ov * ftanh(cn);
            }
            *reinterpret_cast<float2*>(out + (size_t)r * HH + h_base) =
                make_float2(hyv[0], hyv[1]);
            *reinterpret_cast<float2*>(out + (size_t)BB * HH +
                                       (size_t)r * HH + h_base) =
                make_float2(cyv[0], cyv[1]);
        }
    }
}

// ============================================================================
// Host launch
// ============================================================================
typedef CUresult (*cuTensorMapEncodeTiled_t)(
    CUtensorMap*, CUtensorMapDataType, cuuint32_t, void*,
    const cuuint64_t*, const cuuint64_t*, const cuuint32_t*, const cuuint32_t*,
    CUtensorMapInterleave, CUtensorMapSwizzle, CUtensorMapL2promotion,
    CUtensorMapFloatOOBfill);

static void encode_map(cuTensorMapEncodeTiled_t fn, CUtensorMap* m, void* base,
                       unsigned long long rows, unsigned box_rows)
{
    cuuint64_t dims[3]    = {(cuuint64_t)KK, rows, 1};
    cuuint64_t strides[2] = {(cuuint64_t)KK * 2, rows * (cuuint64_t)KK * 2};
    cuuint32_t box[3]     = {TILE_K, box_rows, 1};
    cuuint32_t es[3]      = {1, 1, 1};
    fn(m, CU_TENSOR_MAP_DATA_TYPE_FLOAT16, 3, base, dims, strides, box, es,
       CU_TENSOR_MAP_INTERLEAVE_NONE, CU_TENSOR_MAP_SWIZZLE_128B,
       CU_TENSOR_MAP_L2_PROMOTION_L2_128B, CU_TENSOR_MAP_FLOAT_OOB_FILL_NONE);
}

extern "C" void kernel_launch(void* const* d_in, const int* in_sizes, int n_in,
                              void* d_out, int out_size)
{
    const float* input = (const float*)d_in[0];
    const float* hx    = (const float*)d_in[1];
    const float* cx    = (const float*)d_in[2];
    const float* wih   = (const float*)d_in[3];
    const float* whh   = (const float*)d_in[4];
    const float* bias  = (const float*)d_in[5];
    float* out = (float*)d_out;
    (void)in_sizes; (void)n_in; (void)out_size;

    void *pA, *pW;
    cudaGetSymbolAddress(&pA, g_A);
    cudaGetSymbolAddress(&pW, g_W);

    cuTensorMapEncodeTiled_t enc = nullptr;
    cudaDriverEntryPointQueryResult qr;
    cudaGetDriverEntryPoint("cuTensorMapEncodeTiled", (void**)&enc,
                            cudaEnableDefault, &qr);

    CUtensorMap mA, mW;
    encode_map(enc, &mA, pA, BB,   128);
    encode_map(enc, &mW, pW, NTOT, 256);

    lstm_pack_kernel<<<BB + NTOT, 512>>>(input, hx, wih, whh, bias);

    cudaFuncSetAttribute(lstm_gemm_kernel,
                         cudaFuncAttributeMaxDynamicSharedMemorySize, SMEM_TOTAL);
    lstm_gemm_kernel<<<(BB / TILE_M) * (NTOT / TILE_N), 512, SMEM_TOTAL>>>(
        mA, mW, cx, out);
}

// round 12
// speedup vs baseline: 1.8291x; 1.0053x over previous
#include <cuda_runtime.h>
#include <cuda.h>
#include <cuda_fp16.h>
#include <cstdint>

// ============================================================================
// LSTM cell:  gates = [X|Hx] @ [Wih|Whh]^T + bias ; LSTM epilogue.
//   B=8192, I=H=1024  ->  GEMM M=8192, N=4096, K=2048.
//
// sm_100 (non-'a'): no tcgen05. TMA 4-stage ring -> ldmatrix -> mma.sync
// m16n8k16 fp16, fp32 accum, single fp16 pass (rel_err ~2e-4).
// PERSISTENT: grid = #SMs; each CTA loops over its (mt,nt) tiles with the
// TMA ring streaming k-tiles continuously across tile boundaries.
// CTA 128x256, 512 thr = 16 warps (2M x 8N), warp tile 64x32 (4 warps/SMSP).
// W rows permuted so gates interleave in groups of 8:
//   packed row r: gate=(r>>3)&3, h=(r>>5)*8 + (r&7)
// -> warp's 32-col span = [i|f|g|o] x 8 h; fused in-register LSTM epilogue.
// ============================================================================

#define BB     8192
#define HH     1024
#define KK     2048
#define NTOT   4096

#define TILE_M 128
#define TILE_N 256
#define TILE_K 64       // fp16 elems = 128 bytes = SW128 atom row
#define K_TILES (KK / TILE_K)   // 32
#define N_TILES_TOTAL ((BB / TILE_M) * (NTOT / TILE_N))   // 1024
#define STAGES  4

#define A_BYTES     (128 * 128)              // 16384
#define W_BYTES     (256 * 128)              // 32768
#define STAGE_BYTES (A_BYTES + W_BYTES)      // 49152
#define SM_A 0
#define SM_W 16384

#define SMEM_FULL0  0        // 4 x 8B
#define SMEM_EMPTY0 32       // 4 x 8B
#define SMEM_STAGE0 1024
#define SMEM_TOTAL  (SMEM_STAGE0 + STAGES * STAGE_BYTES)   // 197632

// ---------------- device scratch (no allocation allowed) -------------------
__device__ __align__(1024) __half g_A[(size_t)BB*KK];
__device__ __align__(1024) __half g_W[(size_t)NTOT*KK];
__device__ __align__(16)   float  g_bias_p[NTOT];

// ---------------- PTX helpers ----------------------------------------------
static __device__ __forceinline__ uint32_t smem_u32(const void* p) {
    uint32_t a;
    asm("{ .reg .u64 t; cvta.to.shared.u64 t, %1; cvt.u32.u64 %0, t; }"
        : "=r"(a) : "l"(p));
    return a;
}

#define MBARRIER_INIT(addr, cnt) \
    asm volatile("mbarrier.init.shared.b64 [%0], %1;" :: "r"((uint32_t)(addr)), "r"((uint32_t)(cnt)) : "memory")

#define MBARRIER_ARRIVE(addr) \
    asm volatile("mbarrier.arrive.shared.b64 _, [%0];" :: "r"((uint32_t)(addr)) : "memory")

#define MBARRIER_EXPECT_TX(addr, tx) \
    asm volatile("mbarrier.arrive.expect_tx.shared.b64 _, [%0], %1;" :: "r"((uint32_t)(addr)), "r"((uint32_t)(tx)) : "memory")

#define MBARRIER_WAIT_PARITY(addr, ph) do {                                   \
    uint32_t _m = (uint32_t)(addr); uint32_t _p = (uint32_t)(ph);             \
    asm volatile(                                                             \
        "{\n\t.reg .pred P1;\n\t"                                             \
        "WAIT_LOOP_%=:\n\t"                                                   \
        "mbarrier.try_wait.parity.acquire.cta.shared::cta.b64 P1, [%0], %1, 0x989680;\n\t" \
        "@P1 bra.uni WAIT_DONE_%=;\n\t"                                       \
        "bra.uni WAIT_LOOP_%=;\n\t"                                           \
        "WAIT_DONE_%=:\n\t}"                                                  \
        :: "r"(_m), "r"(_p) : "memory");                                      \
} while (0)

#define TMA_LOAD_3D(smem_addr, tmap, cx_, cy_, cz_, mbar)                      \
    asm volatile(                                                              \
        "cp.async.bulk.tensor.3d.shared::cta.global.tile.mbarrier::complete_tx::bytes " \
        "[%0], [%1, {%2, %3, %4}], [%5];"                                      \
        :: "r"((uint32_t)(smem_addr)), "l"(tmap), "r"((int32_t)(cx_)),         \
           "r"((int32_t)(cy_)), "r"((int32_t)(cz_)), "r"((uint32_t)(mbar))     \
        : "memory")

#define LDMATRIX_X4(r, addr)                                                   \
    asm volatile("ldmatrix.sync.aligned.m8n8.x4.shared.b16 {%0,%1,%2,%3}, [%4];" \
        : "=r"((r)[0]), "=r"((r)[1]), "=r"((r)[2]), "=r"((r)[3])               \
        : "r"(addr))

#define LDMATRIX_X4_B(b0, b1, addr)                                            \
    asm volatile("ldmatrix.sync.aligned.m8n8.x4.shared.b16 {%0,%1,%2,%3}, [%4];" \
        : "=r"((b0)[0]), "=r"((b0)[1]), "=r"((b1)[0]), "=r"((b1)[1])           \
        : "r"(addr))

#define MMA_F16(d, a, b)                                                       \
    asm volatile("mma.sync.aligned.m16n8k16.row.col.f32.f16.f16.f32 "          \
        "{%0,%1,%2,%3}, {%4,%5,%6,%7}, {%8,%9}, {%0,%1,%2,%3};"                \
        : "+f"((d)[0]), "+f"((d)[1]), "+f"((d)[2]), "+f"((d)[3])               \
        : "r"((a)[0]), "r"((a)[1]), "r"((a)[2]), "r"((a)[3]),                  \
          "r"((b)[0]), "r"((b)[1]))

static __device__ __forceinline__ float fsigmoid(float x) {
    return 1.0f / (1.0f + __expf(-x));
}
static __device__ __forceinline__ float ftanh(float x) {
    return 2.0f / (1.0f + __expf(-2.0f * x)) - 1.0f;
}

// ============================================================================
// Kernel 1: pack fp32 -> fp16, concat K, permute W rows, gather bias.
// Packed W row r: gate=(r>>3)&3, h=(r>>5)*8 + (r&7) -> orig = gate*1024 + h.
// ============================================================================
__global__ __launch_bounds__(512) void lstm_pack_kernel(
    const float* __restrict__ input, const float* __restrict__ hx,
    const float* __restrict__ wih,   const float* __restrict__ whh,
    const float* __restrict__ bias)
{
    int row = blockIdx.x;
    int c4  = threadIdx.x * 4;          // 0..2044
    const float* src;
    __half* dst;

    if (row < BB) {
        src = (c4 < HH) ? (input + (size_t)row * HH + c4)
                        : (hx    + (size_t)row * HH + (c4 - HH));
        dst = g_A + (size_t)row * KK + c4;
    } else {
        int r    = row - BB;
        int orig = ((r >> 3) & 3) * 1024 + ((r >> 5) * 8) + (r & 7);
        src = (c4 < HH) ? (wih + (size_t)orig * HH + c4)
                        : (whh + (size_t)orig * HH + (c4 - HH));
        dst = g_W + (size_t)r * KK + c4;
        if (threadIdx.x == 0) g_bias_p[r] = bias[orig];
    }

    float4 v = *reinterpret_cast<const float4*>(src);
    __half2 w01; w01.x = __float2half(v.x); w01.y = __float2half(v.y);
    __half2 w23; w23.x = __float2half(v.z); w23.y = __float2half(v.w);
    reinterpret_cast<__half2*>(dst)[0] = w01;
    reinterpret_cast<__half2*>(dst)[1] = w23;
}

// ============================================================================
// Kernel 2: persistent mma.sync fp16 GEMM + fused LSTM epilogue.
// Grid: #SMs CTAs, 512 threads (16 warps, 2(M) x 8(N)), warp tile 64x32.
// CTA processes tiles blockIdx.x, +grid, +2*grid, ... with one continuous
// TMA ring over the concatenated k-stream of all its tiles.
// ============================================================================
__global__ __launch_bounds__(512, 1) void lstm_gemm_kernel(
    const __grid_constant__ CUtensorMap mapA,
    const __grid_constant__ CUtensorMap mapW,
    const float* __restrict__ cx,
    float* __restrict__ out)
{
    extern __shared__ char smem[];
    const uint32_t sb = smem_u32(smem);
    const int tid  = threadIdx.x;
    const int lane = tid & 31;
    const int wid  = tid >> 5;
    const int wm   = wid >> 3;     // warp row (0-1): 64 rows each
    const int wn   = wid & 7;      // warp col (0-7): 32 cols each

    if (tid == 0) {
#pragma unroll
        for (int s = 0; s < STAGES; s++) {
            MBARRIER_INIT(sb + SMEM_FULL0  + s * 8, 1);
            MBARRIER_INIT(sb + SMEM_EMPTY0 + s * 8, 16);  // one arrive per warp
        }
    }
    __syncthreads();

    const int n_my    = (N_TILES_TOTAL - blockIdx.x + gridDim.x - 1) / gridDim.x;
    const int total_g = n_my * K_TILES;

    // prologue: tid0 fills the ring
    if (tid == 0) {
#pragma unroll
        for (int p = 0; p < STAGES; p++) {
            if (p < total_g) {
                const int tl  = blockIdx.x + (p >> 5) * gridDim.x;
                const uint32_t st = sb + SMEM_STAGE0 + p * STAGE_BYTES;
                const uint32_t fb = sb + SMEM_FULL0 + p * 8;
                MBARRIER_EXPECT_TX(fb, STAGE_BYTES);
                TMA_LOAD_3D(st + SM_A, &mapA, (p & 31) * TILE_K,
                            (tl >> 4) * TILE_M, 0, fb);
                TMA_LOAD_3D(st + SM_W, &mapW, (p & 31) * TILE_K,
                            (tl & 15) * TILE_N, 0, fb);
            }
        }
    }

    // ---- precomputed ldmatrix addressing (SW128: 16B chunk ^= row&7) -------
    const int aChX = lane >> 4;
    const int bChX = (lane >> 3) & 1;
    const int sXor = lane & 7;
    const int aRow = wm * 64 + (lane & 15);
    const int bN   = (lane & 7) + ((lane >> 4) << 3);

    uint32_t aOff[4], bOff[2], chA[4], chB[4];
#pragma unroll
    for (int mt = 0; mt < 4; mt++) aOff[mt] = SM_A + (aRow + mt * 16) * 128;
#pragma unroll
    for (int q = 0; q < 2; q++)   bOff[q]  = SM_W + (wn * 32 + q * 16 + bN) * 128;
#pragma unroll
    for (int ks = 0; ks < 4; ks++) {
        chA[ks] = (uint32_t)(((ks * 2 + aChX) ^ sXor) << 4);
        chB[ks] = (uint32_t)(((ks * 2 + bChX) ^ sXor) << 4);
    }

    int fph[STAGES] = {0, 0, 0, 0}, eph[STAGES] = {0, 0, 0, 0};
    int g = 0;

    for (int ti = 0; ti < n_my; ti++) {
        const int tile = blockIdx.x + ti * gridDim.x;

        float d[4][4][4];                      // [mt][gate][frag]
#pragma unroll
        for (int a = 0; a < 4; a++)
#pragma unroll
            for (int b = 0; b < 4; b++)
#pragma unroll
                for (int c = 0; c < 4; c++) d[a][b][c] = 0.0f;

        for (int t = 0; t < K_TILES; t++, g++) {
            const int s = g & (STAGES - 1);
            const uint32_t stBase = sb + SMEM_STAGE0 + s * STAGE_BYTES;
            MBARRIER_WAIT_PARITY(sb + SMEM_FULL0 + s * 8, fph[s]);
            fph[s] ^= 1;

#pragma unroll
            for (int ks = 0; ks < 4; ks++) {
                const uint32_t sA = stBase + chA[ks];
                const uint32_t sB = stBase + chB[ks];
                uint32_t a[4][4], bw[4][2];
#pragma unroll
                for (int mt = 0; mt < 4; mt++)
                    LDMATRIX_X4(a[mt], sA + aOff[mt]);
#pragma unroll
                for (int q = 0; q < 2; q++)
                    LDMATRIX_X4_B(bw[q*2], bw[q*2 + 1], sB + bOff[q]);
#pragma unroll
                for (int mt = 0; mt < 4; mt++)
#pragma unroll
                    for (int gg = 0; gg < 4; gg++)
                        MMA_F16(d[mt][gg], a[mt], bw[gg]);
            }

            if (lane == 0) MBARRIER_ARRIVE(sb + SMEM_EMPTY0 + s * 8);
            if (tid == 0 && g + STAGES < total_g) {
                MBARRIER_WAIT_PARITY(sb + SMEM_EMPTY0 + s * 8, eph[s]);
                eph[s] ^= 1;
                const int gp  = g + STAGES;
                const int tl  = blockIdx.x + (gp >> 5) * gridDim.x;
                const uint32_t fb = sb + SMEM_FULL0 + s * 8;
                MBARRIER_EXPECT_TX(fb, STAGE_BYTES);
                TMA_LOAD_3D(stBase + SM_A, &mapA, (gp & 31) * TILE_K,
                            (tl >> 4) * TILE_M, 0, fb);
                TMA_LOAD_3D(stBase + SM_W, &mapW, (gp & 31) * TILE_K,
                            (tl & 15) * TILE_N, 0, fb);
            }
        }

        // ---------------- fused in-register LSTM epilogue --------------------
        // Warp's 32 cols = [i|f|g|o] x 8 h;  h-block = nt_blk*8 + wn.
        const int m0     = (tile >> 4) * TILE_M;
        const int wr0    = (tile & 15) * TILE_N;
        const int rbase  = m0 + wm * 64 + (lane >> 2);
        const int h_base = ((tile & 15) * 8 + wn) * 8 + 2 * (lane & 3);
        const int bcol   = wr0 + wn * 32 + 2 * (lane & 3);

        const float2 bi = *reinterpret_cast<const float2*>(g_bias_p + bcol);
        const float2 bf = *reinterpret_cast<const float2*>(g_bias_p + bcol + 8);
        const float2 bg = *reinterpret_cast<const float2*>(g_bias_p + bcol + 16);
        const float2 bo = *reinterpret_cast<const float2*>(g_bias_p + bcol + 24);

#pragma unroll
        for (int mt = 0; mt < 4; mt++) {
#pragma unroll
            for (int half = 0; half < 2; half++) {
                const int r = rbase + mt * 16 + half * 8;
                const float2 c2 = *reinterpret_cast<const float2*>(
                    cx + (size_t)r * HH + h_base);
                float hyv[2], cyv[2];
#pragma unroll
                for (int j = 0; j < 2; j++) {
                    const int fi = half * 2 + j;
                    float gi = d[mt][0][fi] + (j ? bi.y : bi.x);
                    float gf = d[mt][1][fi] + (j ? bf.y : bf.x);
                    float gg = d[mt][2][fi] + (j ? bg.y : bg.x);
                    float go = d[mt][3][fi] + (j ? bo.y : bo.x);
                    float iv = fsigmoid(gi);
                    float fv = fsigmoid(gf);
                    float gv = ftanh(gg);
                    float ov = fsigmoid(go);
                    float cxv = (j == 0) ? c2.x : c2.y;
                    float cn = fv * cxv + iv * gv;
                    cyv[j] = cn;
                    hyv[j] = ov * ftanh(cn);
                }
                *reinterpret_cast<float2*>(out + (size_t)r * HH + h_base) =
                    make_float2(hyv[0], hyv[1]);
                *reinterpret_cast<float2*>(out + (size_t)BB * HH +
                                           (size_t)r * HH + h_base) =
                    make_float2(cyv[0], cyv[1]);
            }
        }
    }
}

// ============================================================================
// Host launch
// ============================================================================
typedef CUresult (*cuTensorMapEncodeTiled_t)(
    CUtensorMap*, CUtensorMapDataType, cuuint32_t, void*,
    const cuuint64_t*, const cuuint64_t*, const cuuint32_t*, const cuuint32_t*,
    CUtensorMapInterleave, CUtensorMapSwizzle, CUtensorMapL2promotion,
    CUtensorMapFloatOOBfill);

static void encode_map(cuTensorMapEncodeTiled_t fn, CUtensorMap* m, void* base,
                       unsigned long long rows, unsigned box_rows)
{
    cuuint64_t dims[3]    = {(cuuint64_t)KK, rows, 1};
    cuuint64_t strides[2] = {(cuuint64_t)KK * 2, rows * (cuuint64_t)KK * 2};
    cuuint32_t box[3]     = {TILE_K, box_rows, 1};
    cuuint32_t es[3]      = {1, 1, 1};
    fn(m, CU_TENSOR_MAP_DATA_TYPE_FLOAT16, 3, base, dims, strides, box, es,
       CU_TENSOR_MAP_INTERLEAVE_NONE, CU_TENSOR_MAP_SWIZZLE_128B,
       CU_TENSOR_MAP_L2_PROMOTION_L2_128B, CU_TENSOR_MAP_FLOAT_OOB_FILL_NONE);
}

extern "C" void kernel_launch(void* const* d_in, const int* in_sizes, int n_in,
                              void* d_out, int out_size)
{
    const float* input = (const float*)d_in[0];
    const float* hx    = (const float*)d_in[1];
    const float* cx    = (const float*)d_in[2];
    const float* wih   = (const float*)d_in[3];
    const float* whh   = (const float*)d_in[4];
    const float* bias  = (const float*)d_in[5];
    float* out = (float*)d_out;
    (void)in_sizes; (void)n_in; (void)out_size;

    void *pA, *pW;
    cudaGetSymbolAddress(&pA, g_A);
    cudaGetSymbolAddress(&pW, g_W);

    cuTensorMapEncodeTiled_t enc = nullptr;
    cudaDriverEntryPointQueryResult qr;
    cudaGetDriverEntryPoint("cuTensorMapEncodeTiled", (void**)&enc,
                            cudaEnableDefault, &qr);

    CUtensorMap mA, mW;
    encode_map(enc, &mA, pA, BB,   128);
    encode_map(enc, &mW, pW, NTOT, 256);

    int nsm = 0;
    cudaDeviceGetAttribute(&nsm, cudaDevAttrMultiProcessorCount, 0);
    if (nsm <= 0) nsm = 148;
    if (nsm > N_TILES_TOTAL) nsm = N_TILES_TOTAL;

    lstm_pack_kernel<<<BB + NTOT, 512>>>(input, hx, wih, whh, bias);

    cudaFuncSetAttribute(lstm_gemm_kernel,
                         cudaFuncAttributeMaxDynamicSharedMemorySize, SMEM_TOTAL);
    lstm_gemm_kernel<<<nsm, 512, SMEM_TOTAL>>>(mA, mW, cx, out);
}